// round 15
// baseline (speedup 1.0000x reference)
#include <cuda_runtime.h>
#include <cuda_fp16.h>
#include <cstdint>

// Problem constants
#define BATCH 128
#define SEQT  512
#define DIN   1024
#define HID   128
#define GATES 512
#define NCLS  8
#define MTOT  (BATCH * SEQT)      // 65536
#define MTILES (MTOT / 128)       // 512
#define NSK0  16                  // hi k-chunks (K=1024/64), layer 0
#define NSK1  2                   // hi k-chunks (K=128/64), layer 1
#define NCHB0 48                  // B stored chunks layer 0 (hi|lo|hi)
#define NCHB1 6                   // B stored chunks layer 1

// ---------------- scratch (device globals; no allocation) ----------------
__device__ __align__(1024) __half g_as[(size_t)MTILES * 2 * NSK0 * 8192]; // 256MB A tiles [hi|lo]
__device__ __align__(1024) __half g_bs0[(size_t)NCHB0 * 32768];           // 3MB  split-fp16 W_ih0
__device__ __align__(1024) __half g_bs1[(size_t)NCHB1 * 32768];           // 384KB split-fp16 W_ih1
__device__ float g_xg[(size_t)MTOT * GATES];   // 128MB gate pre-activations
__device__ float g_h1[(size_t)MTOT * HID];     // 32MB layer-0 hidden states
__device__ float g_hlast[BATCH * HID];

// ---------------- PTX helpers (all sm_103 baseline; NO tcgen05) ----------------
__device__ __forceinline__ uint32_t smem_u32(const void* p) {
    uint32_t a;
    asm("{ .reg .u64 t; cvta.to.shared.u64 t, %1; cvt.u32.u64 %0, t; }" : "=r"(a) : "l"(p));
    return a;
}
__device__ __forceinline__ void mbar_init(uint32_t m, uint32_t cnt) {
    asm volatile("mbarrier.init.shared.b64 [%0], %1;" :: "r"(m), "r"(cnt) : "memory");
}
__device__ __forceinline__ void mbar_expect_tx(uint32_t m, uint32_t b) {
    asm volatile("mbarrier.arrive.expect_tx.shared.b64 _, [%0], %1;" :: "r"(m), "r"(b) : "memory");
}
__device__ __forceinline__ void mbar_wait(uint32_t m, uint32_t ph) {
    asm volatile(
        "{\n\t.reg .pred P;\n\t"
        "WL_%=:\n\t"
        "mbarrier.try_wait.parity.shared.b64 P, [%0], %1;\n\t"
        "@P bra WD_%=;\n\t"
        "bra WL_%=;\n\t"
        "WD_%=:\n\t}"
        :: "r"(m), "r"(ph) : "memory");
}
__device__ __forceinline__ void bulk_g2s(uint32_t dst, const void* src, uint32_t bytes, uint32_t mbar) {
    asm volatile(
        "cp.async.bulk.shared::cluster.global.mbarrier::complete_tx::bytes [%0], [%1], %2, [%3];"
        :: "r"(dst), "l"(src), "r"(bytes), "r"(mbar) : "memory");
}
__device__ __forceinline__ void ldsm_x4(uint32_t& r0, uint32_t& r1, uint32_t& r2, uint32_t& r3,
                                        uint32_t a) {
    asm volatile("ldmatrix.sync.aligned.m8n8.x4.shared.b16 {%0,%1,%2,%3}, [%4];"
        : "=r"(r0), "=r"(r1), "=r"(r2), "=r"(r3) : "r"(a));
}
__device__ __forceinline__ void mma16816(float& d0, float& d1, float& d2, float& d3,
                                         uint32_t a0, uint32_t a1, uint32_t a2, uint32_t a3,
                                         uint32_t b0, uint32_t b1) {
    asm volatile("mma.sync.aligned.m16n8k16.row.col.f32.f16.f16.f32 "
        "{%0,%1,%2,%3},{%4,%5,%6,%7},{%8,%9},{%0,%1,%2,%3};"
        : "+f"(d0), "+f"(d1), "+f"(d2), "+f"(d3)
        : "r"(a0), "r"(a1), "r"(a2), "r"(a3), "r"(b0), "r"(b1));
}

// ---- packed f32x2 FMA (Blackwell FFMA2) ----
typedef unsigned long long u64b;
__device__ __forceinline__ void ffma2(u64b& d, u64b a, u64b b) {
    asm("fma.rn.f32x2 %0, %1, %2, %0;" : "+l"(d) : "l"(a), "l"(b));
}
__device__ __forceinline__ u64b pk64(float x, float y) {
    u64b r; asm("mov.b64 %0, {%1, %2};" : "=l"(r) : "f"(x), "f"(y)); return r;
}
__device__ __forceinline__ float2 upk64(u64b v) {
    float2 r; asm("mov.b64 {%0, %1}, %2;" : "=f"(r.x), "=f"(r.y) : "l"(v)); return r;
}

// ---------------- split-fp16 packing ----------------
__device__ __forceinline__ uint32_t pk2(float f0, float f1, bool lo) {
    __half h0 = __float2half_rn(f0);
    __half h1 = __float2half_rn(f1);
    if (lo) {
        h0 = __float2half_rn(f0 - __half2float(h0));
        h1 = __float2half_rn(f1 - __half2float(h1));
    }
    __half2 p = __halves2half2(h0, h1);
    return *reinterpret_cast<uint32_t*>(&p);
}

// ---------------- conversion: activations -> tiled+swizzled split-fp16 ----------------
// A' storage: [mt][store-chunk][128 x 64 fp16, SW128] 16KB tiles.
// store chunks: first nsk = hi, next nsk = lo (no hi duplication).
__global__ void conv_a_kernel(const float* __restrict__ src, __half* __restrict__ dst,
                              int nstore, int kshift)
{
    int idx = blockIdx.x * 256 + threadIdx.x;
    int u  = idx & 1023;
    int t2 = idx >> 10;
    int c  = t2 % nstore;
    int mt = t2 / nstore;
    int r = u >> 3, g = u & 7;
    int kk = c * 64 + g * 8;           // < 2K
    int slab = kk >> kshift;           // 0 = hi, 1 = lo
    int k = kk - (slab << kshift);
    const float* xr = src + (((size_t)(mt * 128 + r)) << kshift) + k;
    float4 v0 = *(const float4*)xr;
    float4 v1 = *(const float4*)(xr + 4);
    bool lo = (slab == 1);
    uint4 o;
    o.x = pk2(v0.x, v0.y, lo);
    o.y = pk2(v0.z, v0.w, lo);
    o.z = pk2(v1.x, v1.y, lo);
    o.w = pk2(v1.z, v1.w, lo);
    uint32_t ob = (uint32_t)((r << 7) | (g << 4));
    uint32_t so = ob ^ ((ob >> 3) & 0x70);
    char* tile = (char*)(dst + (((size_t)(mt * nstore + c)) << 13));
    *(uint4*)(tile + so) = o;
}

// weights -> [chunk][512 rows x 64 fp16, SW128-swizzled] (64KB chunks)
// stored [hi | lo | hi]; GEMM reads hi from chunks 0..nsk-1 and lo from nsk..2nsk-1.
__global__ void conv_b_kernel(const float* __restrict__ w, __half* __restrict__ dst,
                              int kshift)
{
    int idx = blockIdx.x * 256 + threadIdx.x;
    int g = idx & 7;
    int n = (idx >> 3) & 511;
    int c = idx >> 12;
    int kk = c * 64 + g * 8;
    int slab = kk >> kshift;
    int k = kk - (slab << kshift);
    const float* wr = w + (((size_t)n) << kshift) + k;
    float4 v0 = *(const float4*)wr;
    float4 v1 = *(const float4*)(wr + 4);
    bool lo = (slab == 1);
    uint4 o;
    o.x = pk2(v0.x, v0.y, lo);
    o.y = pk2(v0.z, v0.w, lo);
    o.z = pk2(v1.x, v1.y, lo);
    o.w = pk2(v1.z, v1.w, lo);
    uint32_t ob = (uint32_t)((n << 7) | (g << 4));
    uint32_t so = ob ^ ((ob >> 3) & 0x70);
    char* chunk = (char*)(dst + (((size_t)c) << 15));
    *(uint4*)(chunk + so) = o;
}

// ---------------- HMMA GEMM with slab sharing ----------------
// Stage k (nsk total): Ahi_k 16KB + Alo_k 16KB + Bhi_k 32KB + Blo_k 32KB = 96KB.
// MMAs per kstep: (Ahi+Alo)xBhi then Ahi x Blo -> 48 mma from 12 LDSM (was 16 from 6).
#define GEMM_SMEM 200704
__global__ __launch_bounds__(512, 1) void gemm_hmma_kernel(
    const __half* __restrict__ Ap, const __half* __restrict__ Bp,
    const float* __restrict__ b1, const float* __restrict__ b2,
    float* __restrict__ C, int nsk)
{
    extern __shared__ char smem_raw[];
    uint32_t sb0 = smem_u32(smem_raw);
    uint32_t ab = (sb0 + 1023) & ~1023u;                 // 1024-aligned base
    float* smbias = (float*)(smem_raw + (ab - sb0));     // 512 floats at offset 0

    const int tid = threadIdx.x;
    const int lane = tid & 31, wid = tid >> 5;
    const int wm = wid >> 2, wn = wid & 3;
    const int sub = lane >> 3, l7 = lane & 7;

    if (tid < 512) smbias[tid] = b1[tid] + b2[tid];
    if (tid == 0) {
        mbar_init(ab + 2048, 1); mbar_init(ab + 2056, 1);
    }
    __syncthreads();

    const int mt = blockIdx.x >> 1, j = blockIdx.x & 1;
    const char* Asrc = (const char*)Ap + ((size_t)mt * 2 * nsk) * 16384;
    const char* Bsrc = (const char*)Bp + (size_t)j * 32768;

    if (tid == 0) {
        int npre = nsk < 2 ? nsk : 2;
        for (int c = 0; c < npre; c++) {
            uint32_t st = ab + 4096 + c * 98304;
            uint32_t mb = ab + 2048 + c * 8;
            mbar_expect_tx(mb, 98304);
            bulk_g2s(st,         Asrc + (size_t)c * 16384,         16384, mb);  // A-hi_c
            bulk_g2s(st + 16384, Asrc + (size_t)(nsk + c) * 16384, 16384, mb);  // A-lo_c
            bulk_g2s(st + 32768, Bsrc + (size_t)c * 65536,         32768, mb);  // B-hi_c
            bulk_g2s(st + 65536, Bsrc + (size_t)(nsk + c) * 65536, 32768, mb);  // B-lo_c
        }
    }

    float acc[2][8][4];
#pragma unroll
    for (int a = 0; a < 2; a++)
#pragma unroll
        for (int b = 0; b < 8; b++)
#pragma unroll
            for (int d = 0; d < 4; d++) acc[a][b][d] = 0.0f;

    const uint32_t xorv = (uint32_t)(l7 << 4);
    const uint32_t arow = (uint32_t)((wm * 32 + (sub & 1) * 8 + l7) * 128);
    const uint32_t akh  = (uint32_t)((sub >> 1) * 16);
    const uint32_t brow = (uint32_t)((wn * 64 + (sub >> 1) * 8 + l7) * 128);
    const uint32_t bkh  = (uint32_t)((sub & 1) * 16);

    for (int c = 0; c < nsk; c++) {
        int s = c & 1;
        uint32_t ph = (uint32_t)((c >> 1) & 1);
        uint32_t mb_full = ab + 2048 + s * 8;
        mbar_wait(mb_full, ph);
        uint32_t Ahi = ab + 4096 + s * 98304;
        uint32_t Alo = Ahi + 16384;
        uint32_t Bhi = Ahi + 32768;
        uint32_t Blo = Ahi + 65536;

#pragma unroll
        for (int ks = 0; ks < 4; ks++) {
            uint32_t kw = (uint32_t)(ks * 32);
            uint32_t ak = (kw + akh) ^ xorv;
            uint32_t bk = (kw + bkh) ^ xorv;
            uint32_t ah0[4], ah1[4], al0[4], al1[4], bf[4][4];
            ldsm_x4(ah0[0], ah0[1], ah0[2], ah0[3], Ahi + arow + ak);
            ldsm_x4(ah1[0], ah1[1], ah1[2], ah1[3], Ahi + arow + 2048 + ak);
            ldsm_x4(al0[0], al0[1], al0[2], al0[3], Alo + arow + ak);
            ldsm_x4(al1[0], al1[1], al1[2], al1[3], Alo + arow + 2048 + ak);
            // B-hi: both A slabs accumulate
#pragma unroll
            for (int nb2 = 0; nb2 < 4; nb2++)
                ldsm_x4(bf[nb2][0], bf[nb2][1], bf[nb2][2], bf[nb2][3],
                        Bhi + brow + nb2 * 2048 + bk);
#pragma unroll
            for (int nb = 0; nb < 8; nb++) {
                uint32_t bb0 = bf[nb >> 1][(nb & 1) * 2];
                uint32_t bb1 = bf[nb >> 1][(nb & 1) * 2 + 1];
                mma16816(acc[0][nb][0], acc[0][nb][1], acc[0][nb][2], acc[0][nb][3],
                         ah0[0], ah0[1], ah0[2], ah0[3], bb0, bb1);
                mma16816(acc[1][nb][0], acc[1][nb][1], acc[1][nb][2], acc[1][nb][3],
                         ah1[0], ah1[1], ah1[2], ah1[3], bb0, bb1);
                mma16816(acc[0][nb][0], acc[0][nb][1], acc[0][nb][2], acc[0][nb][3],
                         al0[0], al0[1], al0[2], al0[3], bb0, bb1);
                mma16816(acc[1][nb][0], acc[1][nb][1], acc[1][nb][2], acc[1][nb][3],
                         al1[0], al1[1], al1[2], al1[3], bb0, bb1);
            }
            // B-lo: hi-A only (reuse bf registers)
#pragma unroll
            for (int nb2 = 0; nb2 < 4; nb2++)
                ldsm_x4(bf[nb2][0], bf[nb2][1], bf[nb2][2], bf[nb2][3],
                        Blo + brow + nb2 * 2048 + bk);
#pragma unroll
            for (int nb = 0; nb < 8; nb++) {
                uint32_t bb0 = bf[nb >> 1][(nb & 1) * 2];
                uint32_t bb1 = bf[nb >> 1][(nb & 1) * 2 + 1];
                mma16816(acc[0][nb][0], acc[0][nb][1], acc[0][nb][2], acc[0][nb][3],
                         ah0[0], ah0[1], ah0[2], ah0[3], bb0, bb1);
                mma16816(acc[1][nb][0], acc[1][nb][1], acc[1][nb][2], acc[1][nb][3],
                         ah1[0], ah1[1], ah1[2], ah1[3], bb0, bb1);
            }
        }
        __syncthreads();
        if (tid == 0 && c + 2 < nsk) {
            int cn = c + 2;
            uint32_t st = ab + 4096 + s * 98304;
            mbar_expect_tx(mb_full, 98304);
            bulk_g2s(st,         Asrc + (size_t)cn * 16384,         16384, mb_full);
            bulk_g2s(st + 16384, Asrc + (size_t)(nsk + cn) * 16384, 16384, mb_full);
            bulk_g2s(st + 32768, Bsrc + (size_t)cn * 65536,         32768, mb_full);
            bulk_g2s(st + 65536, Bsrc + (size_t)(nsk + cn) * 65536, 32768, mb_full);
        }
    }

    const int mbase = mt * 128 + wm * 32 + (lane >> 2);
    const int colb  = j * 256 + wn * 64 + (lane & 3) * 2;
#pragma unroll
    for (int mb = 0; mb < 2; mb++)
#pragma unroll
        for (int nb = 0; nb < 8; nb++) {
            int cc = colb + nb * 8;
            float bx = smbias[cc], by = smbias[cc + 1];
            size_t r0 = (size_t)(mbase + mb * 16) * GATES + cc;
            float2 v0 = make_float2(acc[mb][nb][0] + bx, acc[mb][nb][1] + by);
            float2 v1 = make_float2(acc[mb][nb][2] + bx, acc[mb][nb][3] + by);
            *(float2*)(C + r0) = v0;
            *(float2*)(C + r0 + (size_t)8 * GATES) = v1;
        }
}

// ---------------- activations ----------------
__device__ __forceinline__ float sigmoidf_(float x) {
    return __fdividef(1.0f, 1.0f + __expf(-x));
}
__device__ __forceinline__ float tanhf_(float x) {
    float a = __expf(2.0f * fabsf(x));
    float r = 1.0f - __fdividef(2.0f, 1.0f + a);
    return copysignf(r, x);
}

// ---------------- LSTM recurrence: R10-exact (256 thr, 2 gates/thr, 96/32 split) ----------------
#define REC_SMEM (8 * 512 * 16 + 128 * 4 + 512 * 4)
__global__ __launch_bounds__(256, 1) void lstm_rec_kernel(
    const float* __restrict__ xg, const float* __restrict__ w_hh,
    float* __restrict__ hout, float* __restrict__ hlast, int T)
{
    extern __shared__ float smem[];
    float4* sw = (float4*)smem;                 // [kc 0..7][row 0..511] float4 (k=96..127)
    float* h_s = smem + 8 * 512 * 4;            // 128 floats
    float* gates = h_s + 128;                   // 512 floats (activated)

    const int tid = threadIdx.x;
    const int b = blockIdx.x;
    const int rowA = tid;                        // i (0..127) / f (128..255): sigmoid
    const int rowB = tid + 256;                  // g (256..383): tanh / o (384..511): sigmoid
    const bool b_is_tanh = (tid < 128);

    const float4* wrowA = (const float4*)(w_hh + (size_t)rowA * HID);
    const float4* wrowB = (const float4*)(w_hh + (size_t)rowB * HID);
    u64b wrA[48], wrB[48];
#pragma unroll
    for (int i = 0; i < 24; i++) {
        float4 va = wrowA[i];
        wrA[2 * i]     = pk64(va.x, va.y);
        wrA[2 * i + 1] = pk64(va.z, va.w);
        float4 vb = wrowB[i];
        wrB[2 * i]     = pk64(vb.x, vb.y);
        wrB[2 * i + 1] = pk64(vb.z, vb.w);
    }
#pragma unroll
    for (int kc = 0; kc < 8; kc++) {
        sw[kc * 512 + rowA] = wrowA[24 + kc];   // k = 96..127
        sw[kc * 512 + rowB] = wrowB[24 + kc];
    }

    if (tid < HID) h_s[tid] = 0.0f;
    float c = 0.0f;
    __syncthreads();

    const float* xg_bA = xg + ((size_t)b * T) * GATES + rowA;
    const float* xg_bB = xg + ((size_t)b * T) * GATES + rowB;
    float xgA = xg_bA[0];
    float xgB = xg_bB[0];

    for (int t = 0; t < T; t++) {
        float xgA_n = (t + 1 < T) ? xg_bA[(size_t)(t + 1) * GATES] : 0.0f;
        float xgB_n = (t + 1 < T) ? xg_bB[(size_t)(t + 1) * GATES] : 0.0f;

        u64b a0 = pk64(xgA, 0.0f), a1 = pk64(0.0f, 0.0f);
        u64b b0 = pk64(xgB, 0.0f), b1 = pk64(0.0f, 0.0f);
        const ulonglong2* h2 = (const ulonglong2*)h_s;
        // k = 0..95: h broadcast + register weights, 4 independent chains
#pragma unroll
        for (int i = 0; i < 24; i++) {
            ulonglong2 hv = h2[i];
            ffma2(a0, hv.x, wrA[2 * i]);
            ffma2(a1, hv.y, wrA[2 * i + 1]);
            ffma2(b0, hv.x, wrB[2 * i]);
            ffma2(b1, hv.y, wrB[2 * i + 1]);
        }
        // k = 96..127: weights from smem
#pragma unroll
        for (int kc = 0; kc < 8; kc++) {
            ulonglong2 hv = h2[24 + kc];
            float4 wa = sw[kc * 512 + rowA];
            ulonglong2 wau = *reinterpret_cast<ulonglong2*>(&wa);
            ffma2(a0, hv.x, wau.x);
            ffma2(a1, hv.y, wau.y);
            float4 wb = sw[kc * 512 + rowB];
            ulonglong2 wbu = *reinterpret_cast<ulonglong2*>(&wb);
            ffma2(b0, hv.x, wbu.x);
            ffma2(b1, hv.y, wbu.y);
        }
        float2 fa0 = upk64(a0), fa1 = upk64(a1);
        float2 fb0 = upk64(b0), fb1 = upk64(b1);
        float preA = (fa0.x + fa0.y) + (fa1.x + fa1.y);
        float preB = (fb0.x + fb0.y) + (fb1.x + fb1.y);
        gates[rowA] = sigmoidf_(preA);                                // i or f
        gates[rowB] = b_is_tanh ? tanhf_(preB) : sigmoidf_(preB);     // g or o
        __syncthreads();

        if (tid < HID) {
            float ig = gates[tid];
            float fg = gates[HID + tid];
            float gg = gates[2 * HID + tid];
            float og = gates[3 * HID + tid];
            c = fg * c + ig * gg;
            float h = og * tanhf_(c);
            h_s[tid] = h;
            if (hout) hout[((size_t)b * T + t) * HID + tid] = h;
        }
        __syncthreads();
        xgA = xgA_n;
        xgB = xgB_n;
    }
    if (hlast && tid < HID) hlast[b * HID + tid] = h_s[tid];
}

// ---------------- final FC ----------------
__global__ void fc_kernel(const float* __restrict__ hlast, const float* __restrict__ fc_w,
                          const float* __restrict__ fc_b, float* __restrict__ out)
{
    int tid = threadIdx.x;
    int b = tid >> 3;
    int cls = tid & 7;
    const float* hv = hlast + b * HID;
    const float* wv = fc_w + cls * HID;
    float s = fc_b[cls];
#pragma unroll 8
    for (int j = 0; j < HID; j++) s += hv[j] * wv[j];
    out[b * NCLS + cls] = s;
}

// ---------------- launch ----------------
extern "C" void kernel_launch(void* const* d_in, const int* in_sizes, int n_in,
                              void* d_out, int out_size)
{
    const float* x     = (const float*)d_in[0];
    const float* w_ih0 = (const float*)d_in[1];
    const float* w_hh0 = (const float*)d_in[2];
    const float* b_ih0 = (const float*)d_in[3];
    const float* b_hh0 = (const float*)d_in[4];
    const float* w_ih1 = (const float*)d_in[5];
    const float* w_hh1 = (const float*)d_in[6];
    const float* b_ih1 = (const float*)d_in[7];
    const float* b_hh1 = (const float*)d_in[8];
    const float* fc_w  = (const float*)d_in[9];
    const float* fc_b  = (const float*)d_in[10];
    float* out = (float*)d_out;

    float *xg_p = nullptr, *h1_p = nullptr, *hl_p = nullptr;
    __half *as_p = nullptr, *bs0_p = nullptr, *bs1_p = nullptr;
    cudaGetSymbolAddress((void**)&xg_p, g_xg);
    cudaGetSymbolAddress((void**)&h1_p, g_h1);
    cudaGetSymbolAddress((void**)&hl_p, g_hlast);
    cudaGetSymbolAddress((void**)&as_p, g_as);
    cudaGetSymbolAddress((void**)&bs0_p, g_bs0);
    cudaGetSymbolAddress((void**)&bs1_p, g_bs1);

    cudaFuncSetAttribute(lstm_rec_kernel,
                         cudaFuncAttributeMaxDynamicSharedMemorySize, REC_SMEM);
    cudaFuncSetAttribute(gemm_hmma_kernel,
                         cudaFuncAttributeMaxDynamicSharedMemorySize, GEMM_SMEM);

    // weight conversions (tiny; 3-slab storage, GEMM reads hi 0..nsk-1, lo nsk..2nsk-1)
    conv_b_kernel<<<NCHB0 * 512 * 8 / 256, 256>>>(w_ih0, bs0_p, 10);
    conv_b_kernel<<<NCHB1 * 512 * 8 / 256, 256>>>(w_ih1, bs1_p, 7);

    // layer 0: x -> [hi|lo] A tiles -> slab-sharing HMMA GEMM -> recurrence
    conv_a_kernel<<<MTILES * (2 * NSK0) * 1024 / 256, 256>>>(x, as_p, 2 * NSK0, 10);
    gemm_hmma_kernel<<<MTILES * 2, 512, GEMM_SMEM>>>(as_p, bs0_p, b_ih0, b_hh0, xg_p, NSK0);
    lstm_rec_kernel<<<BATCH, 256, REC_SMEM>>>(xg_p, w_hh0, h1_p, nullptr, SEQT);

    // layer 1: h1 -> [hi|lo] A tiles -> GEMM -> recurrence
    conv_a_kernel<<<MTILES * (2 * NSK1) * 1024 / 256, 256>>>(h1_p, as_p, 2 * NSK1, 7);
    gemm_hmma_kernel<<<MTILES * 2, 512, GEMM_SMEM>>>(as_p, bs1_p, b_ih1, b_hh1, xg_p, NSK1);
    lstm_rec_kernel<<<BATCH, 256, REC_SMEM>>>(xg_p, w_hh1, nullptr, hl_p, SEQT);

    // FC head
    fc_kernel<<<1, BATCH * NCLS>>>(hl_p, fc_w, fc_b, out);
}

// round 16
// speedup vs baseline: 1.0414x; 1.0414x over previous
#include <cuda_runtime.h>
#include <cuda_fp16.h>
#include <cstdint>

// Problem constants
#define BATCH 128
#define SEQT  512
#define DIN   1024
#define HID   128
#define GATES 512
#define NCLS  8
#define MTOT  (BATCH * SEQT)      // 65536
#define MTILES (MTOT / 128)       // 512
#define NSK0  16                  // hi k-chunks (K=1024/64), layer 0
#define NSK1  2                   // hi k-chunks (K=128/64), layer 1
#define NCHB0 48                  // B stored chunks layer 0 (hi|lo|hi)
#define NCHB1 6                   // B stored chunks layer 1

// ---------------- scratch (device globals; no allocation) ----------------
__device__ __align__(1024) __half g_as[(size_t)MTILES * 2 * NSK0 * 8192]; // 256MB A tiles [hi|lo]
__device__ __align__(1024) __half g_bs0[(size_t)NCHB0 * 32768];           // 3MB  split-fp16 W_ih0
__device__ __align__(1024) __half g_bs1[(size_t)NCHB1 * 32768];           // 384KB split-fp16 W_ih1
__device__ float g_xg[(size_t)MTOT * GATES];   // 128MB gate pre-activations
__device__ float g_h1[(size_t)MTOT * HID];     // 32MB layer-0 hidden states
__device__ float g_hlast[BATCH * HID];

// ---------------- PTX helpers (all sm_103 baseline; NO tcgen05) ----------------
__device__ __forceinline__ uint32_t smem_u32(const void* p) {
    uint32_t a;
    asm("{ .reg .u64 t; cvta.to.shared.u64 t, %1; cvt.u32.u64 %0, t; }" : "=r"(a) : "l"(p));
    return a;
}
__device__ __forceinline__ void mbar_init(uint32_t m, uint32_t cnt) {
    asm volatile("mbarrier.init.shared.b64 [%0], %1;" :: "r"(m), "r"(cnt) : "memory");
}
__device__ __forceinline__ void mbar_expect_tx(uint32_t m, uint32_t b) {
    asm volatile("mbarrier.arrive.expect_tx.shared.b64 _, [%0], %1;" :: "r"(m), "r"(b) : "memory");
}
__device__ __forceinline__ void mbar_wait(uint32_t m, uint32_t ph) {
    asm volatile(
        "{\n\t.reg .pred P;\n\t"
        "WL_%=:\n\t"
        "mbarrier.try_wait.parity.shared.b64 P, [%0], %1;\n\t"
        "@P bra WD_%=;\n\t"
        "bra WL_%=;\n\t"
        "WD_%=:\n\t}"
        :: "r"(m), "r"(ph) : "memory");
}
__device__ __forceinline__ void bulk_g2s(uint32_t dst, const void* src, uint32_t bytes, uint32_t mbar) {
    asm volatile(
        "cp.async.bulk.shared::cluster.global.mbarrier::complete_tx::bytes [%0], [%1], %2, [%3];"
        :: "r"(dst), "l"(src), "r"(bytes), "r"(mbar) : "memory");
}
__device__ __forceinline__ void ldsm_x4(uint32_t& r0, uint32_t& r1, uint32_t& r2, uint32_t& r3,
                                        uint32_t a) {
    asm volatile("ldmatrix.sync.aligned.m8n8.x4.shared.b16 {%0,%1,%2,%3}, [%4];"
        : "=r"(r0), "=r"(r1), "=r"(r2), "=r"(r3) : "r"(a));
}
__device__ __forceinline__ void mma16816(float& d0, float& d1, float& d2, float& d3,
                                         uint32_t a0, uint32_t a1, uint32_t a2, uint32_t a3,
                                         uint32_t b0, uint32_t b1) {
    asm volatile("mma.sync.aligned.m16n8k16.row.col.f32.f16.f16.f32 "
        "{%0,%1,%2,%3},{%4,%5,%6,%7},{%8,%9},{%0,%1,%2,%3};"
        : "+f"(d0), "+f"(d1), "+f"(d2), "+f"(d3)
        : "r"(a0), "r"(a1), "r"(a2), "r"(a3), "r"(b0), "r"(b1));
}

// ---- packed f32x2 FMA (Blackwell FFMA2) ----
typedef unsigned long long u64b;
__device__ __forceinline__ void ffma2(u64b& d, u64b a, u64b b) {
    asm("fma.rn.f32x2 %0, %1, %2, %0;" : "+l"(d) : "l"(a), "l"(b));
}
__device__ __forceinline__ u64b pk64(float x, float y) {
    u64b r; asm("mov.b64 %0, {%1, %2};" : "=l"(r) : "f"(x), "f"(y)); return r;
}
__device__ __forceinline__ float2 upk64(u64b v) {
    float2 r; asm("mov.b64 {%0, %1}, %2;" : "=f"(r.x), "=f"(r.y) : "l"(v)); return r;
}

// ---------------- split-fp16 packing ----------------
__device__ __forceinline__ uint32_t pk2(float f0, float f1, bool lo) {
    __half h0 = __float2half_rn(f0);
    __half h1 = __float2half_rn(f1);
    if (lo) {
        h0 = __float2half_rn(f0 - __half2float(h0));
        h1 = __float2half_rn(f1 - __half2float(h1));
    }
    __half2 p = __halves2half2(h0, h1);
    return *reinterpret_cast<uint32_t*>(&p);
}
// produce hi and lo packed pairs from one fp32 pair (single conversion chain)
__device__ __forceinline__ void pk2_both(float f0, float f1, uint32_t& hi, uint32_t& lo) {
    __half h0 = __float2half_rn(f0);
    __half h1 = __float2half_rn(f1);
    __half l0 = __float2half_rn(f0 - __half2float(h0));
    __half l1 = __float2half_rn(f1 - __half2float(h1));
    __half2 ph = __halves2half2(h0, h1);
    __half2 pl = __halves2half2(l0, l1);
    hi = *reinterpret_cast<uint32_t*>(&ph);
    lo = *reinterpret_cast<uint32_t*>(&pl);
}

// ---------------- conversion: activations -> tiled+swizzled split-fp16 (FUSED hi+lo) ----------------
// A' storage: [mt][store-chunk][128 x 64 fp16, SW128] 16KB tiles.
// store chunks: c in 0..nsk-1 = hi, nsk..2nsk-1 = lo. ONE source read produces both.
__global__ void conv_a_kernel(const float* __restrict__ src, __half* __restrict__ dst,
                              int nsk, int kshift)
{
    int idx = blockIdx.x * 256 + threadIdx.x;
    int u  = idx & 1023;
    int t2 = idx >> 10;
    int c  = t2 % nsk;                 // hi chunk index (k-chunk)
    int mt = t2 / nsk;
    int r = u >> 3, g = u & 7;
    int k = c * 64 + g * 8;            // within K
    const float* xr = src + (((size_t)(mt * 128 + r)) << kshift) + k;
    float4 v0 = *(const float4*)xr;
    float4 v1 = *(const float4*)(xr + 4);
    uint4 ohi, olo;
    pk2_both(v0.x, v0.y, ohi.x, olo.x);
    pk2_both(v0.z, v0.w, ohi.y, olo.y);
    pk2_both(v1.x, v1.y, ohi.z, olo.z);
    pk2_both(v1.z, v1.w, ohi.w, olo.w);
    uint32_t ob = (uint32_t)((r << 7) | (g << 4));
    uint32_t so = ob ^ ((ob >> 3) & 0x70);
    char* thi = (char*)(dst + (((size_t)(mt * 2 * nsk + c)) << 13));
    char* tlo = (char*)(dst + (((size_t)(mt * 2 * nsk + nsk + c)) << 13));
    *(uint4*)(thi + so) = ohi;
    *(uint4*)(tlo + so) = olo;
}

// weights -> [chunk][512 rows x 64 fp16, SW128-swizzled] (64KB chunks)
// stored [hi | lo | hi]; GEMM reads hi from chunks 0..nsk-1 and lo from nsk..2nsk-1.
__global__ void conv_b_kernel(const float* __restrict__ w, __half* __restrict__ dst,
                              int kshift)
{
    int idx = blockIdx.x * 256 + threadIdx.x;
    int g = idx & 7;
    int n = (idx >> 3) & 511;
    int c = idx >> 12;
    int kk = c * 64 + g * 8;
    int slab = kk >> kshift;
    int k = kk - (slab << kshift);
    const float* wr = w + (((size_t)n) << kshift) + k;
    float4 v0 = *(const float4*)wr;
    float4 v1 = *(const float4*)(wr + 4);
    bool lo = (slab == 1);
    uint4 o;
    o.x = pk2(v0.x, v0.y, lo);
    o.y = pk2(v0.z, v0.w, lo);
    o.z = pk2(v1.x, v1.y, lo);
    o.w = pk2(v1.z, v1.w, lo);
    uint32_t ob = (uint32_t)((n << 7) | (g << 4));
    uint32_t so = ob ^ ((ob >> 3) & 0x70);
    char* chunk = (char*)(dst + (((size_t)c) << 15));
    *(uint4*)(chunk + so) = o;
}

// ---------------- HMMA GEMM with slab sharing (R15, tensor 79.9%) ----------------
// Stage k (nsk total): Ahi_k 16KB + Alo_k 16KB + Bhi_k 32KB + Blo_k 32KB = 96KB.
#define GEMM_SMEM 200704
__global__ __launch_bounds__(512, 1) void gemm_hmma_kernel(
    const __half* __restrict__ Ap, const __half* __restrict__ Bp,
    const float* __restrict__ b1, const float* __restrict__ b2,
    float* __restrict__ C, int nsk)
{
    extern __shared__ char smem_raw[];
    uint32_t sb0 = smem_u32(smem_raw);
    uint32_t ab = (sb0 + 1023) & ~1023u;                 // 1024-aligned base
    float* smbias = (float*)(smem_raw + (ab - sb0));     // 512 floats at offset 0

    const int tid = threadIdx.x;
    const int lane = tid & 31, wid = tid >> 5;
    const int wm = wid >> 2, wn = wid & 3;
    const int sub = lane >> 3, l7 = lane & 7;

    if (tid < 512) smbias[tid] = b1[tid] + b2[tid];
    if (tid == 0) {
        mbar_init(ab + 2048, 1); mbar_init(ab + 2056, 1);
    }
    __syncthreads();

    const int mt = blockIdx.x >> 1, j = blockIdx.x & 1;
    const char* Asrc = (const char*)Ap + ((size_t)mt * 2 * nsk) * 16384;
    const char* Bsrc = (const char*)Bp + (size_t)j * 32768;

    if (tid == 0) {
        int npre = nsk < 2 ? nsk : 2;
        for (int c = 0; c < npre; c++) {
            uint32_t st = ab + 4096 + c * 98304;
            uint32_t mb = ab + 2048 + c * 8;
            mbar_expect_tx(mb, 98304);
            bulk_g2s(st,         Asrc + (size_t)c * 16384,         16384, mb);  // A-hi_c
            bulk_g2s(st + 16384, Asrc + (size_t)(nsk + c) * 16384, 16384, mb);  // A-lo_c
            bulk_g2s(st + 32768, Bsrc + (size_t)c * 65536,         32768, mb);  // B-hi_c
            bulk_g2s(st + 65536, Bsrc + (size_t)(nsk + c) * 65536, 32768, mb);  // B-lo_c
        }
    }

    float acc[2][8][4];
#pragma unroll
    for (int a = 0; a < 2; a++)
#pragma unroll
        for (int b = 0; b < 8; b++)
#pragma unroll
            for (int d = 0; d < 4; d++) acc[a][b][d] = 0.0f;

    const uint32_t xorv = (uint32_t)(l7 << 4);
    const uint32_t arow = (uint32_t)((wm * 32 + (sub & 1) * 8 + l7) * 128);
    const uint32_t akh  = (uint32_t)((sub >> 1) * 16);
    const uint32_t brow = (uint32_t)((wn * 64 + (sub >> 1) * 8 + l7) * 128);
    const uint32_t bkh  = (uint32_t)((sub & 1) * 16);

    for (int c = 0; c < nsk; c++) {
        int s = c & 1;
        uint32_t ph = (uint32_t)((c >> 1) & 1);
        uint32_t mb_full = ab + 2048 + s * 8;
        mbar_wait(mb_full, ph);
        uint32_t Ahi = ab + 4096 + s * 98304;
        uint32_t Alo = Ahi + 16384;
        uint32_t Bhi = Ahi + 32768;
        uint32_t Blo = Ahi + 65536;

#pragma unroll
        for (int ks = 0; ks < 4; ks++) {
            uint32_t kw = (uint32_t)(ks * 32);
            uint32_t ak = (kw + akh) ^ xorv;
            uint32_t bk = (kw + bkh) ^ xorv;
            uint32_t ah0[4], ah1[4], al0[4], al1[4], bf[4][4];
            ldsm_x4(ah0[0], ah0[1], ah0[2], ah0[3], Ahi + arow + ak);
            ldsm_x4(ah1[0], ah1[1], ah1[2], ah1[3], Ahi + arow + 2048 + ak);
            ldsm_x4(al0[0], al0[1], al0[2], al0[3], Alo + arow + ak);
            ldsm_x4(al1[0], al1[1], al1[2], al1[3], Alo + arow + 2048 + ak);
            // B-hi: both A slabs accumulate
#pragma unroll
            for (int nb2 = 0; nb2 < 4; nb2++)
                ldsm_x4(bf[nb2][0], bf[nb2][1], bf[nb2][2], bf[nb2][3],
                        Bhi + brow + nb2 * 2048 + bk);
#pragma unroll
            for (int nb = 0; nb < 8; nb++) {
                uint32_t bb0 = bf[nb >> 1][(nb & 1) * 2];
                uint32_t bb1 = bf[nb >> 1][(nb & 1) * 2 + 1];
                mma16816(acc[0][nb][0], acc[0][nb][1], acc[0][nb][2], acc[0][nb][3],
                         ah0[0], ah0[1], ah0[2], ah0[3], bb0, bb1);
                mma16816(acc[1][nb][0], acc[1][nb][1], acc[1][nb][2], acc[1][nb][3],
                         ah1[0], ah1[1], ah1[2], ah1[3], bb0, bb1);
                mma16816(acc[0][nb][0], acc[0][nb][1], acc[0][nb][2], acc[0][nb][3],
                         al0[0], al0[1], al0[2], al0[3], bb0, bb1);
                mma16816(acc[1][nb][0], acc[1][nb][1], acc[1][nb][2], acc[1][nb][3],
                         al1[0], al1[1], al1[2], al1[3], bb0, bb1);
            }
            // B-lo: hi-A only (reuse bf registers)
#pragma unroll
            for (int nb2 = 0; nb2 < 4; nb2++)
                ldsm_x4(bf[nb2][0], bf[nb2][1], bf[nb2][2], bf[nb2][3],
                        Blo + brow + nb2 * 2048 + bk);
#pragma unroll
            for (int nb = 0; nb < 8; nb++) {
                uint32_t bb0 = bf[nb >> 1][(nb & 1) * 2];
                uint32_t bb1 = bf[nb >> 1][(nb & 1) * 2 + 1];
                mma16816(acc[0][nb][0], acc[0][nb][1], acc[0][nb][2], acc[0][nb][3],
                         ah0[0], ah0[1], ah0[2], ah0[3], bb0, bb1);
                mma16816(acc[1][nb][0], acc[1][nb][1], acc[1][nb][2], acc[1][nb][3],
                         ah1[0], ah1[1], ah1[2], ah1[3], bb0, bb1);
            }
        }
        __syncthreads();
        if (tid == 0 && c + 2 < nsk) {
            int cn = c + 2;
            uint32_t st = ab + 4096 + s * 98304;
            mbar_expect_tx(mb_full, 98304);
            bulk_g2s(st,         Asrc + (size_t)cn * 16384,         16384, mb_full);
            bulk_g2s(st + 16384, Asrc + (size_t)(nsk + cn) * 16384, 16384, mb_full);
            bulk_g2s(st + 32768, Bsrc + (size_t)cn * 65536,         32768, mb_full);
            bulk_g2s(st + 65536, Bsrc + (size_t)(nsk + cn) * 65536, 32768, mb_full);
        }
    }

    const int mbase = mt * 128 + wm * 32 + (lane >> 2);
    const int colb  = j * 256 + wn * 64 + (lane & 3) * 2;
#pragma unroll
    for (int mb = 0; mb < 2; mb++)
#pragma unroll
        for (int nb = 0; nb < 8; nb++) {
            int cc = colb + nb * 8;
            float bx = smbias[cc], by = smbias[cc + 1];
            size_t r0 = (size_t)(mbase + mb * 16) * GATES + cc;
            float2 v0 = make_float2(acc[mb][nb][0] + bx, acc[mb][nb][1] + by);
            float2 v1 = make_float2(acc[mb][nb][2] + bx, acc[mb][nb][3] + by);
            *(float2*)(C + r0) = v0;
            *(float2*)(C + r0 + (size_t)8 * GATES) = v1;
        }
}

// ---------------- activations ----------------
__device__ __forceinline__ float sigmoidf_(float x) {
    return __fdividef(1.0f, 1.0f + __expf(-x));
}
__device__ __forceinline__ float tanhf_(float x) {
    float a = __expf(2.0f * fabsf(x));
    float r = 1.0f - __fdividef(2.0f, 1.0f + a);
    return copysignf(r, x);
}

// ---------------- LSTM recurrence: R10-exact (256 thr, 2 gates/thr, 96/32 split) ----------------
#define REC_SMEM (8 * 512 * 16 + 128 * 4 + 512 * 4)
__global__ __launch_bounds__(256, 1) void lstm_rec_kernel(
    const float* __restrict__ xg, const float* __restrict__ w_hh,
    float* __restrict__ hout, float* __restrict__ hlast, int T)
{
    extern __shared__ float smem[];
    float4* sw = (float4*)smem;                 // [kc 0..7][row 0..511] float4 (k=96..127)
    float* h_s = smem + 8 * 512 * 4;            // 128 floats
    float* gates = h_s + 128;                   // 512 floats (activated)

    const int tid = threadIdx.x;
    const int b = blockIdx.x;
    const int rowA = tid;                        // i (0..127) / f (128..255): sigmoid
    const int rowB = tid + 256;                  // g (256..383): tanh / o (384..511): sigmoid
    const bool b_is_tanh = (tid < 128);

    const float4* wrowA = (const float4*)(w_hh + (size_t)rowA * HID);
    const float4* wrowB = (const float4*)(w_hh + (size_t)rowB * HID);
    u64b wrA[48], wrB[48];
#pragma unroll
    for (int i = 0; i < 24; i++) {
        float4 va = wrowA[i];
        wrA[2 * i]     = pk64(va.x, va.y);
        wrA[2 * i + 1] = pk64(va.z, va.w);
        float4 vb = wrowB[i];
        wrB[2 * i]     = pk64(vb.x, vb.y);
        wrB[2 * i + 1] = pk64(vb.z, vb.w);
    }
#pragma unroll
    for (int kc = 0; kc < 8; kc++) {
        sw[kc * 512 + rowA] = wrowA[24 + kc];   // k = 96..127
        sw[kc * 512 + rowB] = wrowB[24 + kc];
    }

    if (tid < HID) h_s[tid] = 0.0f;
    float c = 0.0f;
    __syncthreads();

    const float* xg_bA = xg + ((size_t)b * T) * GATES + rowA;
    const float* xg_bB = xg + ((size_t)b * T) * GATES + rowB;
    float xgA = xg_bA[0];
    float xgB = xg_bB[0];

    for (int t = 0; t < T; t++) {
        float xgA_n = (t + 1 < T) ? xg_bA[(size_t)(t + 1) * GATES] : 0.0f;
        float xgB_n = (t + 1 < T) ? xg_bB[(size_t)(t + 1) * GATES] : 0.0f;

        u64b a0 = pk64(xgA, 0.0f), a1 = pk64(0.0f, 0.0f);
        u64b b0 = pk64(xgB, 0.0f), b1 = pk64(0.0f, 0.0f);
        const ulonglong2* h2 = (const ulonglong2*)h_s;
        // k = 0..95: h broadcast + register weights, 4 independent chains
#pragma unroll
        for (int i = 0; i < 24; i++) {
            ulonglong2 hv = h2[i];
            ffma2(a0, hv.x, wrA[2 * i]);
            ffma2(a1, hv.y, wrA[2 * i + 1]);
            ffma2(b0, hv.x, wrB[2 * i]);
            ffma2(b1, hv.y, wrB[2 * i + 1]);
        }
        // k = 96..127: weights from smem
#pragma unroll
        for (int kc = 0; kc < 8; kc++) {
            ulonglong2 hv = h2[24 + kc];
            float4 wa = sw[kc * 512 + rowA];
            ulonglong2 wau = *reinterpret_cast<ulonglong2*>(&wa);
            ffma2(a0, hv.x, wau.x);
            ffma2(a1, hv.y, wau.y);
            float4 wb = sw[kc * 512 + rowB];
            ulonglong2 wbu = *reinterpret_cast<ulonglong2*>(&wb);
            ffma2(b0, hv.x, wbu.x);
            ffma2(b1, hv.y, wbu.y);
        }
        float2 fa0 = upk64(a0), fa1 = upk64(a1);
        float2 fb0 = upk64(b0), fb1 = upk64(b1);
        float preA = (fa0.x + fa0.y) + (fa1.x + fa1.y);
        float preB = (fb0.x + fb0.y) + (fb1.x + fb1.y);
        gates[rowA] = sigmoidf_(preA);                                // i or f
        gates[rowB] = b_is_tanh ? tanhf_(preB) : sigmoidf_(preB);     // g or o
        __syncthreads();

        if (tid < HID) {
            float ig = gates[tid];
            float fg = gates[HID + tid];
            float gg = gates[2 * HID + tid];
            float og = gates[3 * HID + tid];
            c = fg * c + ig * gg;
            float h = og * tanhf_(c);
            h_s[tid] = h;
            if (hout) hout[((size_t)b * T + t) * HID + tid] = h;
        }
        __syncthreads();
        xgA = xgA_n;
        xgB = xgB_n;
    }
    if (hlast && tid < HID) hlast[b * HID + tid] = h_s[tid];
}

// ---------------- final FC ----------------
__global__ void fc_kernel(const float* __restrict__ hlast, const float* __restrict__ fc_w,
                          const float* __restrict__ fc_b, float* __restrict__ out)
{
    int tid = threadIdx.x;
    int b = tid >> 3;
    int cls = tid & 7;
    const float* hv = hlast + b * HID;
    const float* wv = fc_w + cls * HID;
    float s = fc_b[cls];
#pragma unroll 8
    for (int j = 0; j < HID; j++) s += hv[j] * wv[j];
    out[b * NCLS + cls] = s;
}

// ---------------- launch ----------------
extern "C" void kernel_launch(void* const* d_in, const int* in_sizes, int n_in,
                              void* d_out, int out_size)
{
    const float* x     = (const float*)d_in[0];
    const float* w_ih0 = (const float*)d_in[1];
    const float* w_hh0 = (const float*)d_in[2];
    const float* b_ih0 = (const float*)d_in[3];
    const float* b_hh0 = (const float*)d_in[4];
    const float* w_ih1 = (const float*)d_in[5];
    const float* w_hh1 = (const float*)d_in[6];
    const float* b_ih1 = (const float*)d_in[7];
    const float* b_hh1 = (const float*)d_in[8];
    const float* fc_w  = (const float*)d_in[9];
    const float* fc_b  = (const float*)d_in[10];
    float* out = (float*)d_out;

    float *xg_p = nullptr, *h1_p = nullptr, *hl_p = nullptr;
    __half *as_p = nullptr, *bs0_p = nullptr, *bs1_p = nullptr;
    cudaGetSymbolAddress((void**)&xg_p, g_xg);
    cudaGetSymbolAddress((void**)&h1_p, g_h1);
    cudaGetSymbolAddress((void**)&hl_p, g_hlast);
    cudaGetSymbolAddress((void**)&as_p, g_as);
    cudaGetSymbolAddress((void**)&bs0_p, g_bs0);
    cudaGetSymbolAddress((void**)&bs1_p, g_bs1);

    cudaFuncSetAttribute(lstm_rec_kernel,
                         cudaFuncAttributeMaxDynamicSharedMemorySize, REC_SMEM);
    cudaFuncSetAttribute(gemm_hmma_kernel,
                         cudaFuncAttributeMaxDynamicSharedMemorySize, GEMM_SMEM);

    // weight conversions (tiny; 3-slab storage, GEMM reads hi 0..nsk-1, lo nsk..2nsk-1)
    conv_b_kernel<<<NCHB0 * 512 * 8 / 256, 256>>>(w_ih0, bs0_p, 10);
    conv_b_kernel<<<NCHB1 * 512 * 8 / 256, 256>>>(w_ih1, bs1_p, 7);

    // layer 0: x -> [hi|lo] A tiles (single source read) -> slab-sharing HMMA GEMM -> recurrence
    conv_a_kernel<<<MTILES * NSK0 * 1024 / 256, 256>>>(x, as_p, NSK0, 10);
    gemm_hmma_kernel<<<MTILES * 2, 512, GEMM_SMEM>>>(as_p, bs0_p, b_ih0, b_hh0, xg_p, NSK0);
    lstm_rec_kernel<<<BATCH, 256, REC_SMEM>>>(xg_p, w_hh0, h1_p, nullptr, SEQT);

    // layer 1: h1 -> [hi|lo] A tiles -> GEMM -> recurrence
    conv_a_kernel<<<MTILES * NSK1 * 1024 / 256, 256>>>(h1_p, as_p, NSK1, 7);
    gemm_hmma_kernel<<<MTILES * 2, 512, GEMM_SMEM>>>(as_p, bs1_p, b_ih1, b_hh1, xg_p, NSK1);
    lstm_rec_kernel<<<BATCH, 256, REC_SMEM>>>(xg_p, w_hh1, nullptr, hl_p, SEQT);

    // FC head
    fc_kernel<<<1, BATCH * NCLS>>>(hl_p, fc_w, fc_b, out);
}

// round 17
// speedup vs baseline: 1.0786x; 1.0358x over previous
#include <cuda_runtime.h>
#include <cuda_fp16.h>
#include <cstdint>

// Problem constants
#define BATCH 128
#define SEQT  512
#define DIN   1024
#define HID   128
#define GATES 512
#define NCLS  8
#define MTOT  (BATCH * SEQT)      // 65536
#define MTILES (MTOT / 128)       // 512
#define NSK0  16                  // hi k-chunks (K=1024/64), layer 0
#define NSK1  2                   // hi k-chunks (K=128/64), layer 1
#define NCHB0 48                  // B stored chunks layer 0 (hi|lo|hi)
#define NCHB1 6                   // B stored chunks layer 1

// ---------------- scratch (device globals; no allocation) ----------------
__device__ __align__(1024) __half g_as[(size_t)MTILES * 2 * NSK0 * 8192]; // 256MB A tiles [hi|lo]
__device__ __align__(1024) __half g_bs0[(size_t)NCHB0 * 32768];           // 3MB  split-fp16 W_ih0
__device__ __align__(1024) __half g_bs1[(size_t)NCHB1 * 32768];           // 384KB split-fp16 W_ih1
__device__ float g_xg[(size_t)MTOT * GATES];   // 128MB gate pre-activations
__device__ float g_h1[(size_t)MTOT * HID];     // 32MB layer-0 hidden states
__device__ float g_hlast[BATCH * HID];

// ---------------- PTX helpers (all sm_103 baseline; NO tcgen05) ----------------
__device__ __forceinline__ uint32_t smem_u32(const void* p) {
    uint32_t a;
    asm("{ .reg .u64 t; cvta.to.shared.u64 t, %1; cvt.u32.u64 %0, t; }" : "=r"(a) : "l"(p));
    return a;
}
__device__ __forceinline__ void mbar_init(uint32_t m, uint32_t cnt) {
    asm volatile("mbarrier.init.shared.b64 [%0], %1;" :: "r"(m), "r"(cnt) : "memory");
}
__device__ __forceinline__ void mbar_expect_tx(uint32_t m, uint32_t b) {
    asm volatile("mbarrier.arrive.expect_tx.shared.b64 _, [%0], %1;" :: "r"(m), "r"(b) : "memory");
}
__device__ __forceinline__ void mbar_wait(uint32_t m, uint32_t ph) {
    asm volatile(
        "{\n\t.reg .pred P;\n\t"
        "WL_%=:\n\t"
        "mbarrier.try_wait.parity.shared.b64 P, [%0], %1;\n\t"
        "@P bra WD_%=;\n\t"
        "bra WL_%=;\n\t"
        "WD_%=:\n\t}"
        :: "r"(m), "r"(ph) : "memory");
}
__device__ __forceinline__ void bulk_g2s(uint32_t dst, const void* src, uint32_t bytes, uint32_t mbar) {
    asm volatile(
        "cp.async.bulk.shared::cluster.global.mbarrier::complete_tx::bytes [%0], [%1], %2, [%3];"
        :: "r"(dst), "l"(src), "r"(bytes), "r"(mbar) : "memory");
}
__device__ __forceinline__ void ldsm_x4(uint32_t& r0, uint32_t& r1, uint32_t& r2, uint32_t& r3,
                                        uint32_t a) {
    asm volatile("ldmatrix.sync.aligned.m8n8.x4.shared.b16 {%0,%1,%2,%3}, [%4];"
        : "=r"(r0), "=r"(r1), "=r"(r2), "=r"(r3) : "r"(a));
}
__device__ __forceinline__ void mma16816(float& d0, float& d1, float& d2, float& d3,
                                         uint32_t a0, uint32_t a1, uint32_t a2, uint32_t a3,
                                         uint32_t b0, uint32_t b1) {
    asm volatile("mma.sync.aligned.m16n8k16.row.col.f32.f16.f16.f32 "
        "{%0,%1,%2,%3},{%4,%5,%6,%7},{%8,%9},{%0,%1,%2,%3};"
        : "+f"(d0), "+f"(d1), "+f"(d2), "+f"(d3)
        : "r"(a0), "r"(a1), "r"(a2), "r"(a3), "r"(b0), "r"(b1));
}

// ---- packed f32x2 FMA (Blackwell FFMA2) ----
typedef unsigned long long u64b;
__device__ __forceinline__ void ffma2(u64b& d, u64b a, u64b b) {
    asm("fma.rn.f32x2 %0, %1, %2, %0;" : "+l"(d) : "l"(a), "l"(b));
}
__device__ __forceinline__ u64b pk64(float x, float y) {
    u64b r; asm("mov.b64 %0, {%1, %2};" : "=l"(r) : "f"(x), "f"(y)); return r;
}
__device__ __forceinline__ float2 upk64(u64b v) {
    float2 r; asm("mov.b64 {%0, %1}, %2;" : "=f"(r.x), "=f"(r.y) : "l"(v)); return r;
}

// ---------------- split-fp16 packing ----------------
__device__ __forceinline__ uint32_t pk2(float f0, float f1, bool lo) {
    __half h0 = __float2half_rn(f0);
    __half h1 = __float2half_rn(f1);
    if (lo) {
        h0 = __float2half_rn(f0 - __half2float(h0));
        h1 = __float2half_rn(f1 - __half2float(h1));
    }
    __half2 p = __halves2half2(h0, h1);
    return *reinterpret_cast<uint32_t*>(&p);
}
// produce hi and lo packed pairs from one fp32 pair (single conversion chain)
__device__ __forceinline__ void pk2_both(float f0, float f1, uint32_t& hi, uint32_t& lo) {
    __half h0 = __float2half_rn(f0);
    __half h1 = __float2half_rn(f1);
    __half l0 = __float2half_rn(f0 - __half2float(h0));
    __half l1 = __float2half_rn(f1 - __half2float(h1));
    __half2 ph = __halves2half2(h0, h1);
    __half2 pl = __halves2half2(l0, l1);
    hi = *reinterpret_cast<uint32_t*>(&ph);
    lo = *reinterpret_cast<uint32_t*>(&pl);
}
// fp16x2 -> packed f32x2 operand
__device__ __forceinline__ u64b h2_to_u64(uint32_t h2bits) {
    __half2 h = *reinterpret_cast<__half2*>(&h2bits);
    float2 f = __half22float2(h);
    return pk64(f.x, f.y);
}

// ---------------- conversion: activations -> tiled+swizzled split-fp16 (FUSED hi+lo) ----------------
// A' storage: [mt][store-chunk][128 x 64 fp16, SW128] 16KB tiles.
// store chunks: c in 0..nsk-1 = hi, nsk..2nsk-1 = lo. ONE source read produces both.
__global__ void conv_a_kernel(const float* __restrict__ src, __half* __restrict__ dst,
                              int nsk, int kshift)
{
    int idx = blockIdx.x * 256 + threadIdx.x;
    int u  = idx & 1023;
    int t2 = idx >> 10;
    int c  = t2 % nsk;                 // hi chunk index (k-chunk)
    int mt = t2 / nsk;
    int r = u >> 3, g = u & 7;
    int k = c * 64 + g * 8;            // within K
    const float* xr = src + (((size_t)(mt * 128 + r)) << kshift) + k;
    float4 v0 = *(const float4*)xr;
    float4 v1 = *(const float4*)(xr + 4);
    uint4 ohi, olo;
    pk2_both(v0.x, v0.y, ohi.x, olo.x);
    pk2_both(v0.z, v0.w, ohi.y, olo.y);
    pk2_both(v1.x, v1.y, ohi.z, olo.z);
    pk2_both(v1.z, v1.w, ohi.w, olo.w);
    uint32_t ob = (uint32_t)((r << 7) | (g << 4));
    uint32_t so = ob ^ ((ob >> 3) & 0x70);
    char* thi = (char*)(dst + (((size_t)(mt * 2 * nsk + c)) << 13));
    char* tlo = (char*)(dst + (((size_t)(mt * 2 * nsk + nsk + c)) << 13));
    *(uint4*)(thi + so) = ohi;
    *(uint4*)(tlo + so) = olo;
}

// weights -> [chunk][512 rows x 64 fp16, SW128-swizzled] (64KB chunks)
// stored [hi | lo | hi]; GEMM reads hi from chunks 0..nsk-1 and lo from nsk..2nsk-1.
__global__ void conv_b_kernel(const float* __restrict__ w, __half* __restrict__ dst,
                              int kshift)
{
    int idx = blockIdx.x * 256 + threadIdx.x;
    int g = idx & 7;
    int n = (idx >> 3) & 511;
    int c = idx >> 12;
    int kk = c * 64 + g * 8;
    int slab = kk >> kshift;
    int k = kk - (slab << kshift);
    const float* wr = w + (((size_t)n) << kshift) + k;
    float4 v0 = *(const float4*)wr;
    float4 v1 = *(const float4*)(wr + 4);
    bool lo = (slab == 1);
    uint4 o;
    o.x = pk2(v0.x, v0.y, lo);
    o.y = pk2(v0.z, v0.w, lo);
    o.z = pk2(v1.x, v1.y, lo);
    o.w = pk2(v1.z, v1.w, lo);
    uint32_t ob = (uint32_t)((n << 7) | (g << 4));
    uint32_t so = ob ^ ((ob >> 3) & 0x70);
    char* chunk = (char*)(dst + (((size_t)c) << 15));
    *(uint4*)(chunk + so) = o;
}

// ---------------- HMMA GEMM with slab sharing (R15/R16, tensor ~80%) ----------------
#define GEMM_SMEM 200704
__global__ __launch_bounds__(512, 1) void gemm_hmma_kernel(
    const __half* __restrict__ Ap, const __half* __restrict__ Bp,
    const float* __restrict__ b1, const float* __restrict__ b2,
    float* __restrict__ C, int nsk)
{
    extern __shared__ char smem_raw[];
    uint32_t sb0 = smem_u32(smem_raw);
    uint32_t ab = (sb0 + 1023) & ~1023u;                 // 1024-aligned base
    float* smbias = (float*)(smem_raw + (ab - sb0));     // 512 floats at offset 0

    const int tid = threadIdx.x;
    const int lane = tid & 31, wid = tid >> 5;
    const int wm = wid >> 2, wn = wid & 3;
    const int sub = lane >> 3, l7 = lane & 7;

    if (tid < 512) smbias[tid] = b1[tid] + b2[tid];
    if (tid == 0) {
        mbar_init(ab + 2048, 1); mbar_init(ab + 2056, 1);
    }
    __syncthreads();

    const int mt = blockIdx.x >> 1, j = blockIdx.x & 1;
    const char* Asrc = (const char*)Ap + ((size_t)mt * 2 * nsk) * 16384;
    const char* Bsrc = (const char*)Bp + (size_t)j * 32768;

    if (tid == 0) {
        int npre = nsk < 2 ? nsk : 2;
        for (int c = 0; c < npre; c++) {
            uint32_t st = ab + 4096 + c * 98304;
            uint32_t mb = ab + 2048 + c * 8;
            mbar_expect_tx(mb, 98304);
            bulk_g2s(st,         Asrc + (size_t)c * 16384,         16384, mb);  // A-hi_c
            bulk_g2s(st + 16384, Asrc + (size_t)(nsk + c) * 16384, 16384, mb);  // A-lo_c
            bulk_g2s(st + 32768, Bsrc + (size_t)c * 65536,         32768, mb);  // B-hi_c
            bulk_g2s(st + 65536, Bsrc + (size_t)(nsk + c) * 65536, 32768, mb);  // B-lo_c
        }
    }

    float acc[2][8][4];
#pragma unroll
    for (int a = 0; a < 2; a++)
#pragma unroll
        for (int b = 0; b < 8; b++)
#pragma unroll
            for (int d = 0; d < 4; d++) acc[a][b][d] = 0.0f;

    const uint32_t xorv = (uint32_t)(l7 << 4);
    const uint32_t arow = (uint32_t)((wm * 32 + (sub & 1) * 8 + l7) * 128);
    const uint32_t akh  = (uint32_t)((sub >> 1) * 16);
    const uint32_t brow = (uint32_t)((wn * 64 + (sub >> 1) * 8 + l7) * 128);
    const uint32_t bkh  = (uint32_t)((sub & 1) * 16);

    for (int c = 0; c < nsk; c++) {
        int s = c & 1;
        uint32_t ph = (uint32_t)((c >> 1) & 1);
        uint32_t mb_full = ab + 2048 + s * 8;
        mbar_wait(mb_full, ph);
        uint32_t Ahi = ab + 4096 + s * 98304;
        uint32_t Alo = Ahi + 16384;
        uint32_t Bhi = Ahi + 32768;
        uint32_t Blo = Ahi + 65536;

#pragma unroll
        for (int ks = 0; ks < 4; ks++) {
            uint32_t kw = (uint32_t)(ks * 32);
            uint32_t ak = (kw + akh) ^ xorv;
            uint32_t bk = (kw + bkh) ^ xorv;
            uint32_t ah0[4], ah1[4], al0[4], al1[4], bf[4][4];
            ldsm_x4(ah0[0], ah0[1], ah0[2], ah0[3], Ahi + arow + ak);
            ldsm_x4(ah1[0], ah1[1], ah1[2], ah1[3], Ahi + arow + 2048 + ak);
            ldsm_x4(al0[0], al0[1], al0[2], al0[3], Alo + arow + ak);
            ldsm_x4(al1[0], al1[1], al1[2], al1[3], Alo + arow + 2048 + ak);
            // B-hi: both A slabs accumulate
#pragma unroll
            for (int nb2 = 0; nb2 < 4; nb2++)
                ldsm_x4(bf[nb2][0], bf[nb2][1], bf[nb2][2], bf[nb2][3],
                        Bhi + brow + nb2 * 2048 + bk);
#pragma unroll
            for (int nb = 0; nb < 8; nb++) {
                uint32_t bb0 = bf[nb >> 1][(nb & 1) * 2];
                uint32_t bb1 = bf[nb >> 1][(nb & 1) * 2 + 1];
                mma16816(acc[0][nb][0], acc[0][nb][1], acc[0][nb][2], acc[0][nb][3],
                         ah0[0], ah0[1], ah0[2], ah0[3], bb0, bb1);
                mma16816(acc[1][nb][0], acc[1][nb][1], acc[1][nb][2], acc[1][nb][3],
                         ah1[0], ah1[1], ah1[2], ah1[3], bb0, bb1);
                mma16816(acc[0][nb][0], acc[0][nb][1], acc[0][nb][2], acc[0][nb][3],
                         al0[0], al0[1], al0[2], al0[3], bb0, bb1);
                mma16816(acc[1][nb][0], acc[1][nb][1], acc[1][nb][2], acc[1][nb][3],
                         al1[0], al1[1], al1[2], al1[3], bb0, bb1);
            }
            // B-lo: hi-A only (reuse bf registers)
#pragma unroll
            for (int nb2 = 0; nb2 < 4; nb2++)
                ldsm_x4(bf[nb2][0], bf[nb2][1], bf[nb2][2], bf[nb2][3],
                        Blo + brow + nb2 * 2048 + bk);
#pragma unroll
            for (int nb = 0; nb < 8; nb++) {
                uint32_t bb0 = bf[nb >> 1][(nb & 1) * 2];
                uint32_t bb1 = bf[nb >> 1][(nb & 1) * 2 + 1];
                mma16816(acc[0][nb][0], acc[0][nb][1], acc[0][nb][2], acc[0][nb][3],
                         ah0[0], ah0[1], ah0[2], ah0[3], bb0, bb1);
                mma16816(acc[1][nb][0], acc[1][nb][1], acc[1][nb][2], acc[1][nb][3],
                         ah1[0], ah1[1], ah1[2], ah1[3], bb0, bb1);
            }
        }
        __syncthreads();
        if (tid == 0 && c + 2 < nsk) {
            int cn = c + 2;
            uint32_t st = ab + 4096 + s * 98304;
            mbar_expect_tx(mb_full, 98304);
            bulk_g2s(st,         Asrc + (size_t)cn * 16384,         16384, mb_full);
            bulk_g2s(st + 16384, Asrc + (size_t)(nsk + cn) * 16384, 16384, mb_full);
            bulk_g2s(st + 32768, Bsrc + (size_t)cn * 65536,         32768, mb_full);
            bulk_g2s(st + 65536, Bsrc + (size_t)(nsk + cn) * 65536, 32768, mb_full);
        }
    }

    const int mbase = mt * 128 + wm * 32 + (lane >> 2);
    const int colb  = j * 256 + wn * 64 + (lane & 3) * 2;
#pragma unroll
    for (int mb = 0; mb < 2; mb++)
#pragma unroll
        for (int nb = 0; nb < 8; nb++) {
            int cc = colb + nb * 8;
            float bx = smbias[cc], by = smbias[cc + 1];
            size_t r0 = (size_t)(mbase + mb * 16) * GATES + cc;
            float2 v0 = make_float2(acc[mb][nb][0] + bx, acc[mb][nb][1] + by);
            float2 v1 = make_float2(acc[mb][nb][2] + bx, acc[mb][nb][3] + by);
            *(float2*)(C + r0) = v0;
            *(float2*)(C + r0 + (size_t)8 * GATES) = v1;
        }
}

// ---------------- activations ----------------
__device__ __forceinline__ float sigmoidf_(float x) {
    return __fdividef(1.0f, 1.0f + __expf(-x));
}
__device__ __forceinline__ float tanhf_(float x) {
    float a = __expf(2.0f * fabsf(x));
    float r = 1.0f - __fdividef(2.0f, 1.0f + a);
    return copysignf(r, x);
}

// ---------------- LSTM recurrence: 96 fp32 weights in regs + 32 fp16 weights in smem ----------------
// R10 structure (256 thr, 2 gates/thr). Smem weights (k=96..127) stored as fp16x2:
// halves the weight-LDS crossbar bytes (512 -> 256 wf/step); upconverted per use on
// the ALU pipe (parallel to FFMA2). Quantizes 32/128 recurrent weights to fp16:
// predicted final rel_err ~1e-4, 10x under threshold.
// swh layout: [q 0..3][row 0..511] uint4 (8 fp16 = k 96+8q .. 103+8q), coalesced LDS.128.
#define REC_SMEM (4 * 512 * 16 + 128 * 4 + 512 * 4)
__global__ __launch_bounds__(256, 1) void lstm_rec_kernel(
    const float* __restrict__ xg, const float* __restrict__ w_hh,
    float* __restrict__ hout, float* __restrict__ hlast, int T)
{
    extern __shared__ float smem[];
    uint4* swh = (uint4*)smem;                  // [q][row] fp16x2 x4 (k=96..127)
    float* h_s = smem + 4 * 512 * 4;            // 128 floats
    float* gates = h_s + 128;                   // 512 floats (activated)

    const int tid = threadIdx.x;
    const int b = blockIdx.x;
    const int rowA = tid;                        // i (0..127) / f (128..255): sigmoid
    const int rowB = tid + 256;                  // g (256..383): tanh / o (384..511): sigmoid
    const bool b_is_tanh = (tid < 128);

    const float4* wrowA = (const float4*)(w_hh + (size_t)rowA * HID);
    const float4* wrowB = (const float4*)(w_hh + (size_t)rowB * HID);
    u64b wrA[48], wrB[48];
#pragma unroll
    for (int i = 0; i < 24; i++) {
        float4 va = wrowA[i];
        wrA[2 * i]     = pk64(va.x, va.y);
        wrA[2 * i + 1] = pk64(va.z, va.w);
        float4 vb = wrowB[i];
        wrB[2 * i]     = pk64(vb.x, vb.y);
        wrB[2 * i + 1] = pk64(vb.z, vb.w);
    }
    // k = 96..127 -> fp16 in smem
#pragma unroll
    for (int q = 0; q < 4; q++) {
        float4 a0 = wrowA[24 + 2 * q], a1 = wrowA[25 + 2 * q];
        uint4 pa;
        pa.x = pk2(a0.x, a0.y, false); pa.y = pk2(a0.z, a0.w, false);
        pa.z = pk2(a1.x, a1.y, false); pa.w = pk2(a1.z, a1.w, false);
        swh[q * 512 + rowA] = pa;
        float4 b0 = wrowB[24 + 2 * q], b1 = wrowB[25 + 2 * q];
        uint4 pb;
        pb.x = pk2(b0.x, b0.y, false); pb.y = pk2(b0.z, b0.w, false);
        pb.z = pk2(b1.x, b1.y, false); pb.w = pk2(b1.z, b1.w, false);
        swh[q * 512 + rowB] = pb;
    }

    if (tid < HID) h_s[tid] = 0.0f;
    float c = 0.0f;
    __syncthreads();

    const float* xg_bA = xg + ((size_t)b * T) * GATES + rowA;
    const float* xg_bB = xg + ((size_t)b * T) * GATES + rowB;
    float xgA = xg_bA[0];
    float xgB = xg_bB[0];

    for (int t = 0; t < T; t++) {
        float xgA_n = (t + 1 < T) ? xg_bA[(size_t)(t + 1) * GATES] : 0.0f;
        float xgB_n = (t + 1 < T) ? xg_bB[(size_t)(t + 1) * GATES] : 0.0f;

        u64b a0 = pk64(xgA, 0.0f), a1 = pk64(0.0f, 0.0f);
        u64b b0 = pk64(xgB, 0.0f), b1 = pk64(0.0f, 0.0f);
        const ulonglong2* h2 = (const ulonglong2*)h_s;
        // k = 0..95: h broadcast + fp32 register weights, 4 independent chains
#pragma unroll
        for (int i = 0; i < 24; i++) {
            ulonglong2 hv = h2[i];
            ffma2(a0, hv.x, wrA[2 * i]);
            ffma2(a1, hv.y, wrA[2 * i + 1]);
            ffma2(b0, hv.x, wrB[2 * i]);
            ffma2(b1, hv.y, wrB[2 * i + 1]);
        }
        // k = 96..127: fp16 weights from smem, upconvert on ALU pipe
#pragma unroll
        for (int q = 0; q < 4; q++) {
            ulonglong2 hv0 = h2[24 + 2 * q];
            ulonglong2 hv1 = h2[25 + 2 * q];
            uint4 wa = swh[q * 512 + rowA];
            ffma2(a0, hv0.x, h2_to_u64(wa.x));
            ffma2(a1, hv0.y, h2_to_u64(wa.y));
            ffma2(a0, hv1.x, h2_to_u64(wa.z));
            ffma2(a1, hv1.y, h2_to_u64(wa.w));
            uint4 wb = swh[q * 512 + rowB];
            ffma2(b0, hv0.x, h2_to_u64(wb.x));
            ffma2(b1, hv0.y, h2_to_u64(wb.y));
            ffma2(b0, hv1.x, h2_to_u64(wb.z));
            ffma2(b1, hv1.y, h2_to_u64(wb.w));
        }
        float2 fa0 = upk64(a0), fa1 = upk64(a1);
        float2 fb0 = upk64(b0), fb1 = upk64(b1);
        float preA = (fa0.x + fa0.y) + (fa1.x + fa1.y);
        float preB = (fb0.x + fb0.y) + (fb1.x + fb1.y);
        gates[rowA] = sigmoidf_(preA);                                // i or f
        gates[rowB] = b_is_tanh ? tanhf_(preB) : sigmoidf_(preB);     // g or o
        __syncthreads();

        if (tid < HID) {
            float ig = gates[tid];
            float fg = gates[HID + tid];
            float gg = gates[2 * HID + tid];
            float og = gates[3 * HID + tid];
            c = fg * c + ig * gg;
            float h = og * tanhf_(c);
            h_s[tid] = h;
            if (hout) hout[((size_t)b * T + t) * HID + tid] = h;
        }
        __syncthreads();
        xgA = xgA_n;
        xgB = xgB_n;
    }
    if (hlast && tid < HID) hlast[b * HID + tid] = h_s[tid];
}

// ---------------- final FC ----------------
__global__ void fc_kernel(const float* __restrict__ hlast, const float* __restrict__ fc_w,
                          const float* __restrict__ fc_b, float* __restrict__ out)
{
    int tid = threadIdx.x;
    int b = tid >> 3;
    int cls = tid & 7;
    const float* hv = hlast + b * HID;
    const float* wv = fc_w + cls * HID;
    float s = fc_b[cls];
#pragma unroll 8
    for (int j = 0; j < HID; j++) s += hv[j] * wv[j];
    out[b * NCLS + cls] = s;
}

// ---------------- launch ----------------
extern "C" void kernel_launch(void* const* d_in, const int* in_sizes, int n_in,
                              void* d_out, int out_size)
{
    const float* x     = (const float*)d_in[0];
    const float* w_ih0 = (const float*)d_in[1];
    const float* w_hh0 = (const float*)d_in[2];
    const float* b_ih0 = (const float*)d_in[3];
    const float* b_hh0 = (const float*)d_in[4];
    const float* w_ih1 = (const float*)d_in[5];
    const float* w_hh1 = (const float*)d_in[6];
    const float* b_ih1 = (const float*)d_in[7];
    const float* b_hh1 = (const float*)d_in[8];
    const float* fc_w  = (const float*)d_in[9];
    const float* fc_b  = (const float*)d_in[10];
    float* out = (float*)d_out;

    float *xg_p = nullptr, *h1_p = nullptr, *hl_p = nullptr;
    __half *as_p = nullptr, *bs0_p = nullptr, *bs1_p = nullptr;
    cudaGetSymbolAddress((void**)&xg_p, g_xg);
    cudaGetSymbolAddress((void**)&h1_p, g_h1);
    cudaGetSymbolAddress((void**)&hl_p, g_hlast);
    cudaGetSymbolAddress((void**)&as_p, g_as);
    cudaGetSymbolAddress((void**)&bs0_p, g_bs0);
    cudaGetSymbolAddress((void**)&bs1_p, g_bs1);

    cudaFuncSetAttribute(lstm_rec_kernel,
                         cudaFuncAttributeMaxDynamicSharedMemorySize, REC_SMEM);
    cudaFuncSetAttribute(gemm_hmma_kernel,
                         cudaFuncAttributeMaxDynamicSharedMemorySize, GEMM_SMEM);

    // weight conversions (tiny; 3-slab storage, GEMM reads hi 0..nsk-1, lo nsk..2nsk-1)
    conv_b_kernel<<<NCHB0 * 512 * 8 / 256, 256>>>(w_ih0, bs0_p, 10);
    conv_b_kernel<<<NCHB1 * 512 * 8 / 256, 256>>>(w_ih1, bs1_p, 7);

    // layer 0: x -> [hi|lo] A tiles (single source read) -> slab-sharing HMMA GEMM -> recurrence
    conv_a_kernel<<<MTILES * NSK0 * 1024 / 256, 256>>>(x, as_p, NSK0, 10);
    gemm_hmma_kernel<<<MTILES * 2, 512, GEMM_SMEM>>>(as_p, bs0_p, b_ih0, b_hh0, xg_p, NSK0);
    lstm_rec_kernel<<<BATCH, 256, REC_SMEM>>>(xg_p, w_hh0, h1_p, nullptr, SEQT);

    // layer 1: h1 -> [hi|lo] A tiles -> GEMM -> recurrence
    conv_a_kernel<<<MTILES * NSK1 * 1024 / 256, 256>>>(h1_p, as_p, NSK1, 7);
    gemm_hmma_kernel<<<MTILES * 2, 512, GEMM_SMEM>>>(as_p, bs1_p, b_ih1, b_hh1, xg_p, NSK1);
    lstm_rec_kernel<<<BATCH, 256, REC_SMEM>>>(xg_p, w_hh1, nullptr, hl_p, SEQT);

    // FC head
    fc_kernel<<<1, BATCH * NCLS>>>(hl_p, fc_w, fc_b, out);
}